// round 10
// baseline (speedup 1.0000x reference)
#include <cuda_runtime.h>
#include <math.h>
#include <stdint.h>

#define B_   16
#define TO_  2048
#define TI_  2048
#define D_   64
#define BM   128
#define BN   64
#define NTH  256
#define NT   (TI_/BN)

// smem layout (bytes). K/V rows padded to 68 words (272B)
// buf b: K at b*34816 (64*272=17408), V at b*34816+17408
// mask:  16 slots * 2048B (slot s = rowsel*8+nf; per-thread 8B at tid*8)
#define SM_M       69632
#define SMEM_BYTES (69632 + 32768)   // 102400

#define QSCALE 0.18033688011112042f  // 0.125 * log2(e)

#define CPA16(dst, src) asm volatile("cp.async.cg.shared.global [%0], [%1], 16;" :: "r"(dst), "l"(src))
#define CPA8(dst, src)  asm volatile("cp.async.ca.shared.global [%0], [%1], 8;"  :: "r"(dst), "l"(src))
#define CPA_COMMIT()    asm volatile("cp.async.commit_group;" ::: "memory")
#define CPA_WAIT(n)     asm volatile("cp.async.wait_group %0;" :: "n"(n) : "memory")

static __device__ __forceinline__ uint32_t smem_u32(const void* p) {
    uint32_t a;
    asm("{ .reg .u64 t; cvta.to.shared.u64 t, %1; cvt.u32.u64 %0, t; }" : "=r"(a) : "l"(p));
    return a;
}
static __device__ __forceinline__ uint32_t tf32rna(float x) {
    uint32_t r; asm("cvt.rna.tf32.f32 %0, %1;" : "=r"(r) : "f"(x)); return r;
}
static __device__ __forceinline__ float ex2f(float x) {
    float y; asm("ex2.approx.ftz.f32 %0, %1;" : "=f"(y) : "f"(x)); return y;
}
static __device__ __forceinline__ uint32_t lds32(uint32_t a) {
    uint32_t v; asm volatile("ld.shared.b32 %0, [%1];" : "=r"(v) : "r"(a)); return v;
}
static __device__ __forceinline__ int2 lds64i(uint32_t a) {
    int2 v; asm volatile("ld.shared.v2.b32 {%0,%1}, [%2];" : "=r"(v.x), "=r"(v.y) : "r"(a)); return v;
}
static __device__ __forceinline__ float4 lds128f(uint32_t a) {
    float4 v;
    asm volatile("ld.shared.v4.f32 {%0,%1,%2,%3}, [%4];"
                 : "=f"(v.x), "=f"(v.y), "=f"(v.z), "=f"(v.w) : "r"(a));
    return v;
}
static __device__ __forceinline__ void sts128u(uint32_t a, uint32_t x, uint32_t y,
                                               uint32_t z, uint32_t w) {
    asm volatile("st.shared.v4.b32 [%0], {%1,%2,%3,%4};"
                 :: "r"(a), "r"(x), "r"(y), "r"(z), "r"(w) : "memory");
}
static __device__ __forceinline__ void ldm4(uint32_t& r0, uint32_t& r1, uint32_t& r2,
                                            uint32_t& r3, uint32_t a) {
    asm volatile("ldmatrix.sync.aligned.m8n8.x4.shared.b16 {%0,%1,%2,%3}, [%4];"
                 : "=r"(r0), "=r"(r1), "=r"(r2), "=r"(r3) : "r"(a));
}
static __device__ __forceinline__ void mma_tf32(float* c, uint32_t a0, uint32_t a1,
                                                uint32_t a2, uint32_t a3,
                                                uint32_t b0, uint32_t b1) {
    asm volatile(
        "mma.sync.aligned.m16n8k8.row.col.f32.tf32.tf32.f32 "
        "{%0,%1,%2,%3}, {%4,%5,%6,%7}, {%8,%9}, {%0,%1,%2,%3};"
        : "+f"(c[0]), "+f"(c[1]), "+f"(c[2]), "+f"(c[3])
        : "r"(a0), "r"(a1), "r"(a2), "r"(a3), "r"(b0), "r"(b1));
}

__global__ __launch_bounds__(NTH, 2)
void attn_hmma(const float* __restrict__ Q, const float* __restrict__ K,
               const float* __restrict__ V, const int* __restrict__ M,
               float* __restrict__ O)
{
    extern __shared__ char smem[];
    const uint32_t sb = smem_u32(smem);
    const int tid  = threadIdx.x;
    const int w    = tid >> 5;
    const int lane = tid & 31;
    const int q4   = lane & 3;        // quad lane
    const int r4   = lane >> 2;       // 0..7
    const int b    = blockIdx.y;
    const int q0   = blockIdx.x * BM;

    const float* Qb = Q + ((size_t)b * TO_ + q0) * D_;
    const float* Kb = K + (size_t)b * TI_ * D_;
    const float* Vb = V + (size_t)b * TI_ * D_;
    const int*   Mb = M + ((size_t)b * TO_ + q0) * TI_;
    float*       Ob = O + ((size_t)b * TO_ + q0) * D_;

    // ---- stage K/V tile 0 into buffer 0 (raw) ----
#pragma unroll
    for (int i = 0; i < 4; i++) {
        int idx = tid + i * NTH;
        int row = idx >> 4;
        int c4  = idx & 15;
        CPA16(sb + row * 272 + c4 * 16,          (const char*)(Kb + (size_t)row * D_) + c4 * 16);
        CPA16(sb + 17408 + row * 272 + c4 * 16,  (const char*)(Vb + (size_t)row * D_) + c4 * 16);
    }
    CPA_COMMIT();

    // ---- Q fragments (once, scale*log2e folded, tf32 rna) ----
    uint32_t qa[8][4];
    {
        const float* qp = Qb + (size_t)(w * 16 + r4) * D_ + q4;
#pragma unroll
        for (int kf = 0; kf < 8; kf++) {
            qa[kf][0] = tf32rna(QSCALE * qp[kf * 8]);
            qa[kf][1] = tf32rna(QSCALE * qp[kf * 8 + 8 * D_]);
            qa[kf][2] = tf32rna(QSCALE * qp[kf * 8 + 4]);
            qa[kf][3] = tf32rna(QSCALE * qp[kf * 8 + 4 + 8 * D_]);
        }
    }

    float oc[8][4];
#pragma unroll
    for (int nf = 0; nf < 8; nf++)
#pragma unroll
        for (int i = 0; i < 4; i++) oc[nf][i] = 0.f;
    float l0 = 0.f, l1 = 0.f;

    // ldmatrix per-thread address constant (rows of 4 sub-tiles)
    const uint32_t ldmc = (uint32_t)(lane & 7) * 272 + (uint32_t)((lane >> 3) & 1) * 16
                        + (uint32_t)(lane >> 4) * 2176;

    CPA_WAIT(0);
    // rewrite tile 0 (own chunks) to tf32-rna
#pragma unroll
    for (int i = 0; i < 4; i++) {
        int idx = tid + i * NTH;
        uint32_t a = sb + (idx >> 4) * 272 + (idx & 15) * 16;
        float4 f = lds128f(a);
        sts128u(a, tf32rna(f.x), tf32rna(f.y), tf32rna(f.z), tf32rna(f.w));
        a += 17408;
        f = lds128f(a);
        sts128u(a, tf32rna(f.x), tf32rna(f.y), tf32rna(f.z), tf32rna(f.w));
    }
    __syncthreads();

    const int myrow = w * 16 + r4;

    for (int t = 0; t < NT; t++) {
        const uint32_t sK = sb + (uint32_t)(t & 1) * 34816;
        const uint32_t sV = sK + 17408;

        // ---- self-staged mask(t): 16 x 8B per thread — group 1 ----
#pragma unroll
        for (int s = 0; s < 16; s++) {
            int rs = s >> 3, nf = s & 7;
            uint32_t dst = sb + SM_M + (uint32_t)s * 2048 + (uint32_t)tid * 8;
            const char* src = (const char*)(Mb + (size_t)(myrow + rs * 8) * TI_
                                            + (size_t)t * BN + nf * 8 + 2 * q4);
            CPA8(dst, src);
        }
        CPA_COMMIT();
        // ---- stage K/V(t+1) raw — group 2 ----
        if (t + 1 < NT) {
            const uint32_t sKn = sb + (uint32_t)((t + 1) & 1) * 34816;
            const float* Kg = Kb + (size_t)(t + 1) * BN * D_;
            const float* Vg = Vb + (size_t)(t + 1) * BN * D_;
#pragma unroll
            for (int i = 0; i < 4; i++) {
                int idx = tid + i * NTH;
                int row = idx >> 4;
                int c4  = idx & 15;
                CPA16(sKn + row * 272 + c4 * 16,         (const char*)(Kg + (size_t)row * D_) + c4 * 16);
                CPA16(sKn + 17408 + row * 272 + c4 * 16, (const char*)(Vg + (size_t)row * D_) + c4 * 16);
            }
        }
        CPA_COMMIT();

        // ---- GEMM1: S = Q K^T (ldmatrix.x4 B-frags) ----
        float sc[8][4];
#pragma unroll
        for (int nf = 0; nf < 8; nf++)
#pragma unroll
            for (int i = 0; i < 4; i++) sc[nf][i] = 0.f;

#pragma unroll
        for (int kf = 0; kf < 8; kf++) {
#pragma unroll
            for (int nfp = 0; nfp < 4; nfp++) {
                uint32_t b0, b1, b2, b3;
                ldm4(b0, b1, b2, b3, sK + ldmc + (uint32_t)nfp * 4352 + (uint32_t)kf * 32);
                mma_tf32(sc[2 * nfp],     qa[kf][0], qa[kf][1], qa[kf][2], qa[kf][3], b0, b1);
                mma_tf32(sc[2 * nfp + 1], qa[kf][0], qa[kf][1], qa[kf][2], qa[kf][3], b2, b3);
            }
        }

        CPA_WAIT(1);          // own mask copies done (KV prefetch still in flight)

        // ---- mask + exp2 + tf32-rna (P stays in sc; l from rounded p) ----
#pragma unroll
        for (int nf = 0; nf < 8; nf++) {
            const uint32_t ma = sb + SM_M + (uint32_t)nf * 2048 + (uint32_t)tid * 8;
            const int2 mlo = lds64i(ma);
            const int2 mhi = lds64i(ma + 16384);
            float p0 = (mlo.x != 0) ? ex2f(sc[nf][0]) : 0.f;
            float p1 = (mlo.y != 0) ? ex2f(sc[nf][1]) : 0.f;
            float p2 = (mhi.x != 0) ? ex2f(sc[nf][2]) : 0.f;
            float p3 = (mhi.y != 0) ? ex2f(sc[nf][3]) : 0.f;
            p0 = __uint_as_float(tf32rna(p0));
            p1 = __uint_as_float(tf32rna(p1));
            p2 = __uint_as_float(tf32rna(p2));
            p3 = __uint_as_float(tf32rna(p3));
            l0 += p0 + p1;
            l1 += p2 + p3;
            sc[nf][0] = p0; sc[nf][1] = p1; sc[nf][2] = p2; sc[nf][3] = p3;
        }

        // ---- GEMM2: O += P V (P C-frag -> A-frag via quad shuffles) ----
        const int s0 = (lane & ~3) | (q4 >> 1);
        const int s2 = s0 + 2;
        const bool odd = (q4 & 1) != 0;
#pragma unroll
        for (int kf = 0; kf < 8; kf++) {
            float t00 = __shfl_sync(0xffffffffu, sc[kf][0], s0);
            float t01 = __shfl_sync(0xffffffffu, sc[kf][1], s0);
            float t10 = __shfl_sync(0xffffffffu, sc[kf][2], s0);
            float t11 = __shfl_sync(0xffffffffu, sc[kf][3], s0);
            float t20 = __shfl_sync(0xffffffffu, sc[kf][0], s2);
            float t21 = __shfl_sync(0xffffffffu, sc[kf][1], s2);
            float t30 = __shfl_sync(0xffffffffu, sc[kf][2], s2);
            float t31 = __shfl_sync(0xffffffffu, sc[kf][3], s2);
            uint32_t a0 = __float_as_uint(odd ? t01 : t00);
            uint32_t a1 = __float_as_uint(odd ? t11 : t10);
            uint32_t a2 = __float_as_uint(odd ? t21 : t20);
            uint32_t a3 = __float_as_uint(odd ? t31 : t30);
#pragma unroll
            for (int nf = 0; nf < 8; nf++) {
                uint32_t va = sV + (uint32_t)(kf * 8 + q4) * 272 + (uint32_t)(nf * 8 + r4) * 4;
                uint32_t b0 = lds32(va);
                uint32_t b1 = lds32(va + 4 * 272);
                mma_tf32(oc[nf], a0, a1, a2, a3, b0, b1);
            }
        }

        CPA_WAIT(0);          // KV(t+1) landed (own copies)
        if (t + 1 < NT) {     // rewrite own chunks of next buffer to tf32-rna
            const uint32_t sKn = sb + (uint32_t)((t + 1) & 1) * 34816;
#pragma unroll
            for (int i = 0; i < 4; i++) {
                int idx = tid + i * NTH;
                uint32_t a = sKn + (idx >> 4) * 272 + (idx & 15) * 16;
                float4 f = lds128f(a);
                sts128u(a, tf32rna(f.x), tf32rna(f.y), tf32rna(f.z), tf32rna(f.w));
                a += 17408;
                f = lds128f(a);
                sts128u(a, tf32rna(f.x), tf32rna(f.y), tf32rna(f.z), tf32rna(f.w));
            }
        }
        __syncthreads();      // publish rewritten KV(t+1) to all warps
    }

    // ---- epilogue: row sums + normalize + store ----
    l0 += __shfl_xor_sync(0xffffffffu, l0, 1);
    l0 += __shfl_xor_sync(0xffffffffu, l0, 2);
    l1 += __shfl_xor_sync(0xffffffffu, l1, 1);
    l1 += __shfl_xor_sync(0xffffffffu, l1, 2);
    const float inv0 = 1.f / l0;
    const float inv1 = 1.f / l1;

    float* orow0 = Ob + (size_t)(w * 16 + r4) * D_ + 2 * q4;
    float* orow1 = orow0 + 8 * D_;
#pragma unroll
    for (int nf = 0; nf < 8; nf++) {
        float2 v0 = make_float2(oc[nf][0] * inv0, oc[nf][1] * inv0);
        float2 v1 = make_float2(oc[nf][2] * inv1, oc[nf][3] * inv1);
        *(float2*)(orow0 + nf * 8) = v0;
        *(float2*)(orow1 + nf * 8) = v1;
    }
}

extern "C" void kernel_launch(void* const* d_in, const int* in_sizes, int n_in,
                              void* d_out, int out_size) {
    const float* q = (const float*)d_in[0];
    const float* k = (const float*)d_in[1];
    const float* v = (const float*)d_in[2];
    const int*   m = (const int*)d_in[3];
    float* o = (float*)d_out;

    cudaFuncSetAttribute(attn_hmma, cudaFuncAttributeMaxDynamicSharedMemorySize, SMEM_BYTES);
    dim3 grid(TO_ / BM, B_);
    attn_hmma<<<grid, NTH, SMEM_BYTES>>>(q, k, v, m, o);
}

// round 11
// speedup vs baseline: 1.1758x; 1.1758x over previous
#include <cuda_runtime.h>
#include <math.h>
#include <stdint.h>

#define B_   16
#define TO_  2048
#define TI_  2048
#define D_   64
#define BM   128
#define BN   64
#define NTH  256
#define NT   (TI_/BN)

// smem layout (bytes). K/V rows padded to 72 words (288B) -> GEMM2 conflict-free
// buf b at b*36864: K at +0 (64*288=18432), V at +18432
// mask at 73728: 128 rows * 272B = 34816
#define BUFSZ      36864
#define SM_M       73728
#define SMEM_BYTES (73728 + 34816)   // 108544

#define QSCALE 0.18033688011112042f  // 0.125 * log2(e)

#define CPA16(dst, src) asm volatile("cp.async.cg.shared.global [%0], [%1], 16;" :: "r"(dst), "l"(src))
#define CPA_COMMIT()    asm volatile("cp.async.commit_group;" ::: "memory")
#define CPA_WAIT(n)     asm volatile("cp.async.wait_group %0;" :: "n"(n) : "memory")

static __device__ __forceinline__ uint32_t smem_u32(const void* p) {
    uint32_t a;
    asm("{ .reg .u64 t; cvta.to.shared.u64 t, %1; cvt.u32.u64 %0, t; }" : "=r"(a) : "l"(p));
    return a;
}
static __device__ __forceinline__ uint32_t tf32rna(float x) {
    uint32_t r; asm("cvt.rna.tf32.f32 %0, %1;" : "=r"(r) : "f"(x)); return r;
}
static __device__ __forceinline__ float ex2f(float x) {
    float y; asm("ex2.approx.ftz.f32 %0, %1;" : "=f"(y) : "f"(x)); return y;
}
static __device__ __forceinline__ uint32_t lds32(uint32_t a) {
    uint32_t v; asm volatile("ld.shared.b32 %0, [%1];" : "=r"(v) : "r"(a)); return v;
}
static __device__ __forceinline__ int2 lds64i(uint32_t a) {
    int2 v; asm volatile("ld.shared.v2.b32 {%0,%1}, [%2];" : "=r"(v.x), "=r"(v.y) : "r"(a)); return v;
}
static __device__ __forceinline__ float4 lds128f(uint32_t a) {
    float4 v;
    asm volatile("ld.shared.v4.f32 {%0,%1,%2,%3}, [%4];"
                 : "=f"(v.x), "=f"(v.y), "=f"(v.z), "=f"(v.w) : "r"(a));
    return v;
}
static __device__ __forceinline__ void sts128u(uint32_t a, uint32_t x, uint32_t y,
                                               uint32_t z, uint32_t w) {
    asm volatile("st.shared.v4.b32 [%0], {%1,%2,%3,%4};"
                 :: "r"(a), "r"(x), "r"(y), "r"(z), "r"(w) : "memory");
}
static __device__ __forceinline__ void ldm4(uint32_t& r0, uint32_t& r1, uint32_t& r2,
                                            uint32_t& r3, uint32_t a) {
    asm volatile("ldmatrix.sync.aligned.m8n8.x4.shared.b16 {%0,%1,%2,%3}, [%4];"
                 : "=r"(r0), "=r"(r1), "=r"(r2), "=r"(r3) : "r"(a));
}
static __device__ __forceinline__ void mma_tf32(float* c, uint32_t a0, uint32_t a1,
                                                uint32_t a2, uint32_t a3,
                                                uint32_t b0, uint32_t b1) {
    asm volatile(
        "mma.sync.aligned.m16n8k8.row.col.f32.tf32.tf32.f32 "
        "{%0,%1,%2,%3}, {%4,%5,%6,%7}, {%8,%9}, {%0,%1,%2,%3};"
        : "+f"(c[0]), "+f"(c[1]), "+f"(c[2]), "+f"(c[3])
        : "r"(a0), "r"(a1), "r"(a2), "r"(a3), "r"(b0), "r"(b1));
}

__global__ __launch_bounds__(NTH, 2)
void attn_hmma(const float* __restrict__ Q, const float* __restrict__ K,
               const float* __restrict__ V, const int* __restrict__ M,
               float* __restrict__ O)
{
    extern __shared__ char smem[];
    const uint32_t sb = smem_u32(smem);
    const int tid  = threadIdx.x;
    const int w    = tid >> 5;
    const int lane = tid & 31;
    const int q4   = lane & 3;        // quad lane
    const int r4   = lane >> 2;       // 0..7
    const int b    = blockIdx.y;
    const int q0   = blockIdx.x * BM;

    const float* Qb = Q + ((size_t)b * TO_ + q0) * D_;
    const float* Kb = K + (size_t)b * TI_ * D_;
    const float* Vb = V + (size_t)b * TI_ * D_;
    const int*   Mb = M + ((size_t)b * TO_ + q0) * TI_;
    float*       Ob = O + ((size_t)b * TO_ + q0) * D_;

    // ---- stage K/V tile 0 into buffer 0 ----
#pragma unroll
    for (int i = 0; i < 4; i++) {
        int idx = tid + i * NTH;            // 0..1023 chunk ids
        int row = idx >> 4;
        int c4  = idx & 15;
        CPA16(sb + row * 288 + c4 * 16,          (const char*)(Kb + (size_t)row * D_) + c4 * 16);
        CPA16(sb + 18432 + row * 288 + c4 * 16,  (const char*)(Vb + (size_t)row * D_) + c4 * 16);
    }
    CPA_COMMIT();

    // ---- Q fragments (once, scale*log2e folded, tf32 rna) ----
    uint32_t qa[8][4];
    {
        const float* qp = Qb + (size_t)(w * 16 + r4) * D_ + q4;
#pragma unroll
        for (int kf = 0; kf < 8; kf++) {
            qa[kf][0] = tf32rna(QSCALE * qp[kf * 8]);
            qa[kf][1] = tf32rna(QSCALE * qp[kf * 8 + 8 * D_]);
            qa[kf][2] = tf32rna(QSCALE * qp[kf * 8 + 4]);
            qa[kf][3] = tf32rna(QSCALE * qp[kf * 8 + 4 + 8 * D_]);
        }
    }

    float oc[8][4];
#pragma unroll
    for (int nf = 0; nf < 8; nf++)
#pragma unroll
        for (int i = 0; i < 4; i++) oc[nf][i] = 0.f;
    float l0 = 0.f, l1 = 0.f;

    // ldmatrix per-thread source row (288B K-row stride)
    const uint32_t ldmc = (uint32_t)(lane & 7) * 288 + (uint32_t)((lane >> 3) & 1) * 16
                        + (uint32_t)(lane >> 4) * 2304;

    CPA_WAIT(0);
    // rewrite own V(0) chunks to tf32-rna (self-visible, no barrier needed)
#pragma unroll
    for (int i = 0; i < 4; i++) {
        int idx = tid + i * NTH;
        uint32_t a = sb + 18432 + (idx >> 4) * 288 + (idx & 15) * 16;
        float4 f = lds128f(a);
        sts128u(a, tf32rna(f.x), tf32rna(f.y), tf32rna(f.z), tf32rna(f.w));
    }
    __syncthreads();

    for (int t = 0; t < NT; t++) {
        const uint32_t sK = sb + (uint32_t)(t & 1) * BUFSZ;
        const uint32_t sV = sK + 18432;

        // ---- stage mask(t) rows cooperatively — group 1 ----
        {
            const char* Mg = (const char*)(Mb + (size_t)t * BN);
#pragma unroll
            for (int i = 0; i < 8; i++) {
                int chunk = tid + i * NTH;   // 0..2047 (128 rows x 16 chunks)
                int row = chunk >> 4;
                int c4  = chunk & 15;
                CPA16(sb + SM_M + row * 272 + c4 * 16, Mg + (size_t)row * (TI_ * 4) + c4 * 16);
            }
        }
        CPA_COMMIT();
        // ---- stage K/V(t+1) — group 2 ----
        if (t + 1 < NT) {
            const uint32_t sKn = sb + (uint32_t)((t + 1) & 1) * BUFSZ;
            const float* Kg = Kb + (size_t)(t + 1) * BN * D_;
            const float* Vg = Vb + (size_t)(t + 1) * BN * D_;
#pragma unroll
            for (int i = 0; i < 4; i++) {
                int idx = tid + i * NTH;
                int row = idx >> 4;
                int c4  = idx & 15;
                CPA16(sKn + row * 288 + c4 * 16,         (const char*)(Kg + (size_t)row * D_) + c4 * 16);
                CPA16(sKn + 18432 + row * 288 + c4 * 16, (const char*)(Vg + (size_t)row * D_) + c4 * 16);
            }
        }
        CPA_COMMIT();

        // ---- GEMM1: S = Q K^T (ldmatrix.x4 B-frags) ----
        float sc[8][4];
#pragma unroll
        for (int nf = 0; nf < 8; nf++)
#pragma unroll
            for (int i = 0; i < 4; i++) sc[nf][i] = 0.f;

#pragma unroll
        for (int kf = 0; kf < 8; kf++) {
#pragma unroll
            for (int nfp = 0; nfp < 4; nfp++) {
                uint32_t b0, b1, b2, b3;
                ldm4(b0, b1, b2, b3, sK + ldmc + (uint32_t)nfp * 4608 + (uint32_t)kf * 32);
                mma_tf32(sc[2 * nfp],     qa[kf][0], qa[kf][1], qa[kf][2], qa[kf][3], b0, b1);
                mma_tf32(sc[2 * nfp + 1], qa[kf][0], qa[kf][1], qa[kf][2], qa[kf][3], b2, b3);
            }
        }

        CPA_WAIT(1);          // mask staged (KV prefetch still in flight)
        __syncthreads();      // mask rows from other threads visible

        // ---- mask + exp2 + tf32-rna (P stays in sc; l from ROUNDED p) ----
        {
            const uint32_t mbase = sb + SM_M + (uint32_t)(w * 16 + r4) * 272 + (uint32_t)(2 * q4) * 4;
#pragma unroll
            for (int nf = 0; nf < 8; nf++) {
                const uint32_t ma = mbase + nf * 32;
                const int2 mlo = lds64i(ma);
                const int2 mhi = lds64i(ma + 8 * 272);
                float p0 = (mlo.x != 0) ? ex2f(sc[nf][0]) : 0.f;
                float p1 = (mlo.y != 0) ? ex2f(sc[nf][1]) : 0.f;
                float p2 = (mhi.x != 0) ? ex2f(sc[nf][2]) : 0.f;
                float p3 = (mhi.y != 0) ? ex2f(sc[nf][3]) : 0.f;
                p0 = __uint_as_float(tf32rna(p0));
                p1 = __uint_as_float(tf32rna(p1));
                p2 = __uint_as_float(tf32rna(p2));
                p3 = __uint_as_float(tf32rna(p3));
                l0 += p0 + p1;
                l1 += p2 + p3;
                sc[nf][0] = p0; sc[nf][1] = p1; sc[nf][2] = p2; sc[nf][3] = p3;
            }
        }

        // ---- GEMM2: O += P V (P C-frag -> A-frag via quad shuffles) ----
        const int s0 = (lane & ~3) | (q4 >> 1);
        const int s2 = s0 + 2;
        const bool odd = (q4 & 1) != 0;
#pragma unroll
        for (int kf = 0; kf < 8; kf++) {
            float t00 = __shfl_sync(0xffffffffu, sc[kf][0], s0);
            float t01 = __shfl_sync(0xffffffffu, sc[kf][1], s0);
            float t10 = __shfl_sync(0xffffffffu, sc[kf][2], s0);
            float t11 = __shfl_sync(0xffffffffu, sc[kf][3], s0);
            float t20 = __shfl_sync(0xffffffffu, sc[kf][0], s2);
            float t21 = __shfl_sync(0xffffffffu, sc[kf][1], s2);
            float t30 = __shfl_sync(0xffffffffu, sc[kf][2], s2);
            float t31 = __shfl_sync(0xffffffffu, sc[kf][3], s2);
            uint32_t a0 = __float_as_uint(odd ? t01 : t00);
            uint32_t a1 = __float_as_uint(odd ? t11 : t10);
            uint32_t a2 = __float_as_uint(odd ? t21 : t20);
            uint32_t a3 = __float_as_uint(odd ? t31 : t30);
#pragma unroll
            for (int nf = 0; nf < 8; nf++) {
                uint32_t va = sV + (uint32_t)(kf * 8 + q4) * 288 + (uint32_t)(nf * 8 + r4) * 4;
                uint32_t b0 = lds32(va);
                uint32_t b1 = lds32(va + 4 * 288);
                mma_tf32(oc[nf], a0, a1, a2, a3, b0, b1);
            }
        }

        CPA_WAIT(0);          // KV(t+1) landed
        if (t + 1 < NT) {     // rewrite own V(t+1) chunks to tf32-rna
            const uint32_t sVn = sb + (uint32_t)((t + 1) & 1) * BUFSZ + 18432;
#pragma unroll
            for (int i = 0; i < 4; i++) {
                int idx = tid + i * NTH;
                uint32_t a = sVn + (idx >> 4) * 288 + (idx & 15) * 16;
                float4 f = lds128f(a);
                sts128u(a, tf32rna(f.x), tf32rna(f.y), tf32rna(f.z), tf32rna(f.w));
            }
        }
        __syncthreads();      // publish KV(t+1); mask buffer reusable
    }

    // ---- epilogue: quad row sums + normalize + store ----
    l0 += __shfl_xor_sync(0xffffffffu, l0, 1);
    l0 += __shfl_xor_sync(0xffffffffu, l0, 2);
    l1 += __shfl_xor_sync(0xffffffffu, l1, 1);
    l1 += __shfl_xor_sync(0xffffffffu, l1, 2);
    const float inv0 = 1.f / l0;
    const float inv1 = 1.f / l1;

    float* orow0 = Ob + (size_t)(w * 16 + r4) * D_ + 2 * q4;
    float* orow1 = orow0 + 8 * D_;
#pragma unroll
    for (int nf = 0; nf < 8; nf++) {
        float2 v0 = make_float2(oc[nf][0] * inv0, oc[nf][1] * inv0);
        float2 v1 = make_float2(oc[nf][2] * inv1, oc[nf][3] * inv1);
        *(float2*)(orow0 + nf * 8) = v0;
        *(float2*)(orow1 + nf * 8) = v1;
    }
}

extern "C" void kernel_launch(void* const* d_in, const int* in_sizes, int n_in,
                              void* d_out, int out_size) {
    const float* q = (const float*)d_in[0];
    const float* k = (const float*)d_in[1];
    const float* v = (const float*)d_in[2];
    const int*   m = (const int*)d_in[3];
    float* o = (float*)d_out;

    cudaFuncSetAttribute(attn_hmma, cudaFuncAttributeMaxDynamicSharedMemorySize, SMEM_BYTES);
    dim3 grid(TO_ / BM, B_);
    attn_hmma<<<grid, NTH, SMEM_BYTES>>>(q, k, v, m, o);
}

// round 14
// speedup vs baseline: 1.3092x; 1.1135x over previous
#include <cuda_runtime.h>
#include <math.h>
#include <stdint.h>

#define B_   16
#define TO_  2048
#define TI_  2048
#define D_   64
#define BM   128
#define BN   64
#define NTH  256
#define NT   (TI_/BN)

// smem layout (bytes).
// K rows padded to 272B (68 words, ldmatrix conflict-free: 4r mod 32 distinct)
// V rows padded to 288B (72 words, GEMM2 lds32 conflict-free: 8*q4+r4 distinct)
// buf b at b*35840: K at +0 (64*272=17408), V at +17408 (64*288=18432)
// mask at 71680: 128 rows * 272B = 34816
#define KSTR   272
#define VSTR   288
#define KTILE  17408
#define BUFSZ  35840
#define SM_M   71680
#define SMEM_BYTES (71680 + 34816)   // 106496

#define QSCALE 0.18033688011112042f  // 0.125 * log2(e)

#define CPA16(dst, src) asm volatile("cp.async.cg.shared.global [%0], [%1], 16;" :: "r"(dst), "l"(src))
#define CPA_COMMIT()    asm volatile("cp.async.commit_group;" ::: "memory")
#define CPA_WAIT(n)     asm volatile("cp.async.wait_group %0;" :: "n"(n) : "memory")

static __device__ __forceinline__ uint32_t smem_u32(const void* p) {
    uint32_t a;
    asm("{ .reg .u64 t; cvta.to.shared.u64 t, %1; cvt.u32.u64 %0, t; }" : "=r"(a) : "l"(p));
    return a;
}
static __device__ __forceinline__ uint32_t tf32rna(float x) {
    uint32_t r; asm("cvt.rna.tf32.f32 %0, %1;" : "=r"(r) : "f"(x)); return r;
}
static __device__ __forceinline__ float ex2f(float x) {
    float y; asm("ex2.approx.ftz.f32 %0, %1;" : "=f"(y) : "f"(x)); return y;
}
static __device__ __forceinline__ uint32_t lds32(uint32_t a) {
    uint32_t v; asm volatile("ld.shared.b32 %0, [%1];" : "=r"(v) : "r"(a)); return v;
}
static __device__ __forceinline__ int2 lds64i(uint32_t a) {
    int2 v; asm volatile("ld.shared.v2.b32 {%0,%1}, [%2];" : "=r"(v.x), "=r"(v.y) : "r"(a)); return v;
}
static __device__ __forceinline__ float4 lds128f(uint32_t a) {
    float4 v;
    asm volatile("ld.shared.v4.f32 {%0,%1,%2,%3}, [%4];"
                 : "=f"(v.x), "=f"(v.y), "=f"(v.z), "=f"(v.w) : "r"(a));
    return v;
}
static __device__ __forceinline__ void sts128u(uint32_t a, uint32_t x, uint32_t y,
                                               uint32_t z, uint32_t w) {
    asm volatile("st.shared.v4.b32 [%0], {%1,%2,%3,%4};"
                 :: "r"(a), "r"(x), "r"(y), "r"(z), "r"(w) : "memory");
}
static __device__ __forceinline__ void ldm4(uint32_t& r0, uint32_t& r1, uint32_t& r2,
                                            uint32_t& r3, uint32_t a) {
    asm volatile("ldmatrix.sync.aligned.m8n8.x4.shared.b16 {%0,%1,%2,%3}, [%4];"
                 : "=r"(r0), "=r"(r1), "=r"(r2), "=r"(r3) : "r"(a));
}
static __device__ __forceinline__ void mma_tf32(float* c, uint32_t a0, uint32_t a1,
                                                uint32_t a2, uint32_t a3,
                                                uint32_t b0, uint32_t b1) {
    asm volatile(
        "mma.sync.aligned.m16n8k8.row.col.f32.tf32.tf32.f32 "
        "{%0,%1,%2,%3}, {%4,%5,%6,%7}, {%8,%9}, {%0,%1,%2,%3};"
        : "+f"(c[0]), "+f"(c[1]), "+f"(c[2]), "+f"(c[3])
        : "r"(a0), "r"(a1), "r"(a2), "r"(a3), "r"(b0), "r"(b1));
}

__global__ __launch_bounds__(NTH, 2)
void attn_hmma(const float* __restrict__ Q, const float* __restrict__ K,
               const float* __restrict__ V, const int* __restrict__ M,
               float* __restrict__ O)
{
    extern __shared__ char smem[];
    const uint32_t sb = smem_u32(smem);
    const int tid  = threadIdx.x;
    const int w    = tid >> 5;
    const int lane = tid & 31;
    const int q4   = lane & 3;        // quad lane
    const int r4   = lane >> 2;       // 0..7
    const int b    = blockIdx.y;
    const int q0   = blockIdx.x * BM;

    const float* Qb = Q + ((size_t)b * TO_ + q0) * D_;
    const float* Kb = K + (size_t)b * TI_ * D_;
    const float* Vb = V + (size_t)b * TI_ * D_;
    const int*   Mb = M + ((size_t)b * TO_ + q0) * TI_;
    float*       Ob = O + ((size_t)b * TO_ + q0) * D_;

    // ---- stage K/V tile 0 into buffer 0 ----
#pragma unroll
    for (int i = 0; i < 4; i++) {
        int idx = tid + i * NTH;            // 0..1023 chunk ids
        int row = idx >> 4;
        int c4  = idx & 15;
        CPA16(sb + row * KSTR + c4 * 16,          (const char*)(Kb + (size_t)row * D_) + c4 * 16);
        CPA16(sb + KTILE + row * VSTR + c4 * 16,  (const char*)(Vb + (size_t)row * D_) + c4 * 16);
    }
    CPA_COMMIT();

    // ---- Q fragments (once, scale*log2e folded, tf32 rna) ----
    uint32_t qa[8][4];
    {
        const float* qp = Qb + (size_t)(w * 16 + r4) * D_ + q4;
#pragma unroll
        for (int kf = 0; kf < 8; kf++) {
            qa[kf][0] = tf32rna(QSCALE * qp[kf * 8]);
            qa[kf][1] = tf32rna(QSCALE * qp[kf * 8 + 8 * D_]);
            qa[kf][2] = tf32rna(QSCALE * qp[kf * 8 + 4]);
            qa[kf][3] = tf32rna(QSCALE * qp[kf * 8 + 4 + 8 * D_]);
        }
    }

    float oc[8][4];
#pragma unroll
    for (int nf = 0; nf < 8; nf++)
#pragma unroll
        for (int i = 0; i < 4; i++) oc[nf][i] = 0.f;
    float l0 = 0.f, l1 = 0.f;

    // ldmatrix per-thread source row (272B K-row stride, conflict-free)
    const uint32_t ldmc = (uint32_t)(lane & 7) * KSTR + (uint32_t)((lane >> 3) & 1) * 16
                        + (uint32_t)(lane >> 4) * (8 * KSTR);

    CPA_WAIT(0);
    // rewrite own K/V(0) chunks to tf32-rna (self-visible before barrier)
#pragma unroll
    for (int i = 0; i < 4; i++) {
        int idx = tid + i * NTH;
        uint32_t ak = sb + (idx >> 4) * KSTR + (idx & 15) * 16;
        float4 f = lds128f(ak);
        sts128u(ak, tf32rna(f.x), tf32rna(f.y), tf32rna(f.z), tf32rna(f.w));
        uint32_t av = sb + KTILE + (idx >> 4) * VSTR + (idx & 15) * 16;
        f = lds128f(av);
        sts128u(av, tf32rna(f.x), tf32rna(f.y), tf32rna(f.z), tf32rna(f.w));
    }
    __syncthreads();

    for (int t = 0; t < NT; t++) {
        const uint32_t sK = sb + (uint32_t)(t & 1) * BUFSZ;
        const uint32_t sV = sK + KTILE;

        // ---- stage mask(t) rows cooperatively — group 1 ----
        {
            const char* Mg = (const char*)(Mb + (size_t)t * BN);
#pragma unroll
            for (int i = 0; i < 8; i++) {
                int chunk = tid + i * NTH;   // 0..2047 (128 rows x 16 chunks)
                int row = chunk >> 4;
                int c4  = chunk & 15;
                CPA16(sb + SM_M + row * 272 + c4 * 16, Mg + (size_t)row * (TI_ * 4) + c4 * 16);
            }
        }
        CPA_COMMIT();
        // ---- stage K/V(t+1) — group 2 ----
        if (t + 1 < NT) {
            const uint32_t sKn = sb + (uint32_t)((t + 1) & 1) * BUFSZ;
            const float* Kg = Kb + (size_t)(t + 1) * BN * D_;
            const float* Vg = Vb + (size_t)(t + 1) * BN * D_;
#pragma unroll
            for (int i = 0; i < 4; i++) {
                int idx = tid + i * NTH;
                int row = idx >> 4;
                int c4  = idx & 15;
                CPA16(sKn + row * KSTR + c4 * 16,          (const char*)(Kg + (size_t)row * D_) + c4 * 16);
                CPA16(sKn + KTILE + row * VSTR + c4 * 16,  (const char*)(Vg + (size_t)row * D_) + c4 * 16);
            }
        }
        CPA_COMMIT();

        // ---- GEMM1: S = Q K^T (ldmatrix.x4 B-frags, conflict-free) ----
        float sc[8][4];
#pragma unroll
        for (int nf = 0; nf < 8; nf++)
#pragma unroll
            for (int i = 0; i < 4; i++) sc[nf][i] = 0.f;

#pragma unroll
        for (int kf = 0; kf < 8; kf++) {
#pragma unroll
            for (int nfp = 0; nfp < 4; nfp++) {
                uint32_t b0, b1, b2, b3;
                ldm4(b0, b1, b2, b3, sK + ldmc + (uint32_t)nfp * (16 * KSTR) + (uint32_t)kf * 32);
                mma_tf32(sc[2 * nfp],     qa[kf][0], qa[kf][1], qa[kf][2], qa[kf][3], b0, b1);
                mma_tf32(sc[2 * nfp + 1], qa[kf][0], qa[kf][1], qa[kf][2], qa[kf][3], b2, b3);
            }
        }

        CPA_WAIT(1);          // mask staged (KV prefetch still in flight)
        __syncthreads();      // mask rows from other threads visible

        // ---- mask + exp2 + tf32-rna (P stays in sc; l from ROUNDED p) ----
        {
            const uint32_t mbase = sb + SM_M + (uint32_t)(w * 16 + r4) * 272 + (uint32_t)(2 * q4) * 4;
#pragma unroll
            for (int nf = 0; nf < 8; nf++) {
                const uint32_t ma = mbase + nf * 32;
                const int2 mlo = lds64i(ma);
                const int2 mhi = lds64i(ma + 8 * 272);
                float p0 = (mlo.x != 0) ? ex2f(sc[nf][0]) : 0.f;
                float p1 = (mlo.y != 0) ? ex2f(sc[nf][1]) : 0.f;
                float p2 = (mhi.x != 0) ? ex2f(sc[nf][2]) : 0.f;
                float p3 = (mhi.y != 0) ? ex2f(sc[nf][3]) : 0.f;
                p0 = __uint_as_float(tf32rna(p0));
                p1 = __uint_as_float(tf32rna(p1));
                p2 = __uint_as_float(tf32rna(p2));
                p3 = __uint_as_float(tf32rna(p3));
                l0 += p0 + p1;
                l1 += p2 + p3;
                sc[nf][0] = p0; sc[nf][1] = p1; sc[nf][2] = p2; sc[nf][3] = p3;
            }
        }

        // ---- GEMM2: O += P V (P C-frag -> A-frag via quad shuffles) ----
        const int s0 = (lane & ~3) | (q4 >> 1);
        const int s2 = s0 + 2;
        const bool odd = (q4 & 1) != 0;
#pragma unroll
        for (int kf = 0; kf < 8; kf++) {
            float t00 = __shfl_sync(0xffffffffu, sc[kf][0], s0);
            float t01 = __shfl_sync(0xffffffffu, sc[kf][1], s0);
            float t10 = __shfl_sync(0xffffffffu, sc[kf][2], s0);
            float t11 = __shfl_sync(0xffffffffu, sc[kf][3], s0);
            float t20 = __shfl_sync(0xffffffffu, sc[kf][0], s2);
            float t21 = __shfl_sync(0xffffffffu, sc[kf][1], s2);
            float t30 = __shfl_sync(0xffffffffu, sc[kf][2], s2);
            float t31 = __shfl_sync(0xffffffffu, sc[kf][3], s2);
            uint32_t a0 = __float_as_uint(odd ? t01 : t00);
            uint32_t a1 = __float_as_uint(odd ? t11 : t10);
            uint32_t a2 = __float_as_uint(odd ? t21 : t20);
            uint32_t a3 = __float_as_uint(odd ? t31 : t30);
#pragma unroll
            for (int nf = 0; nf < 8; nf++) {
                uint32_t va = sV + (uint32_t)(kf * 8 + q4) * VSTR + (uint32_t)(nf * 8 + r4) * 4;
                uint32_t b0 = lds32(va);
                uint32_t b1 = lds32(va + 4 * VSTR);
                mma_tf32(oc[nf], a0, a1, a2, a3, b0, b1);
            }
        }

        CPA_WAIT(0);          // KV(t+1) landed
        if (t + 1 < NT) {     // rewrite own K/V(t+1) chunks to tf32-rna
            const uint32_t sKn = sb + (uint32_t)((t + 1) & 1) * BUFSZ;
#pragma unroll
            for (int i = 0; i < 4; i++) {
                int idx = tid + i * NTH;
                uint32_t ak = sKn + (idx >> 4) * KSTR + (idx & 15) * 16;
                float4 f = lds128f(ak);
                sts128u(ak, tf32rna(f.x), tf32rna(f.y), tf32rna(f.z), tf32rna(f.w));
                uint32_t av = sKn + KTILE + (idx >> 4) * VSTR + (idx & 15) * 16;
                f = lds128f(av);
                sts128u(av, tf32rna(f.x), tf32rna(f.y), tf32rna(f.z), tf32rna(f.w));
            }
        }
        __syncthreads();      // publish KV(t+1); mask buffer reusable
    }

    // ---- epilogue: quad row sums + normalize + store ----
    l0 += __shfl_xor_sync(0xffffffffu, l0, 1);
    l0 += __shfl_xor_sync(0xffffffffu, l0, 2);
    l1 += __shfl_xor_sync(0xffffffffu, l1, 1);
    l1 += __shfl_xor_sync(0xffffffffu, l1, 2);
    const float inv0 = 1.f / l0;
    const float inv1 = 1.f / l1;

    float* orow0 = Ob + (size_t)(w * 16 + r4) * D_ + 2 * q4;
    float* orow1 = orow0 + 8 * D_;
#pragma unroll
    for (int nf = 0; nf < 8; nf++) {
        float2 v0 = make_float2(oc[nf][0] * inv0, oc[nf][1] * inv0);
        float2 v1 = make_float2(oc[nf][2] * inv1, oc[nf][3] * inv1);
        *(float2*)(orow0 + nf * 8) = v0;
        *(float2*)(orow1 + nf * 8) = v1;
    }
}

extern "C" void kernel_launch(void* const* d_in, const int* in_sizes, int n_in,
                              void* d_out, int out_size) {
    const float* q = (const float*)d_in[0];
    const float* k = (const float*)d_in[1];
    const float* v = (const float*)d_in[2];
    const int*   m = (const int*)d_in[3];
    float* o = (float*)d_out;

    cudaFuncSetAttribute(attn_hmma, cudaFuncAttributeMaxDynamicSharedMemorySize, SMEM_BYTES);
    dim3 grid(TO_ / BM, B_);
    attn_hmma<<<grid, NTH, SMEM_BYTES>>>(q, k, v, m, o);
}